// round 13
// baseline (speedup 1.0000x reference)
#include <cuda_runtime.h>
#include <cstdint>

#define NPTS 4096
#define DDIM 64
#define KPW 36      // bf16 tile stride in uint32 kpairs: conflict-free
#define SLD 132     // staging stride (floats): banks 8t+g conflict-free
#define NBLOCKS 272 // pair-tile blocks (256 pairs + 16 diagonal singles)
#define NDUTY 16    // duty CTAs = the 16 diagonal singletons

#define WGBAR(w) asm volatile("bar.sync %0, %1;" :: "r"((w) + 1), "r"(128) : "memory")

// ---------------- device scratch (zero-init; counters self-reset) ----------------
__device__ float g_partial_sq[NDUTY];
__device__ float g_partial_col[NDUTY][64];
__device__ float g_c;
__device__ int   g_arrive = 0;
__device__ int   g_done   = 0;
__device__ unsigned int g_flag = 0;

__device__ __forceinline__ uint32_t bf2(float lo, float hi) {
    uint32_t o;
    asm("cvt.rn.bf16x2.f32 %0, %1, %2;" : "=r"(o) : "f"(hi), "f"(lo));
    return o;
}

// ---- bf16 m16n8k16 mma; Bs is row-indexed by (warpCol + n*8 + g) ----
__device__ __forceinline__ void mma_tile(const uint32_t* As, const uint32_t* Bs,
                                         int warpRow, int warpCol, int g, int t,
                                         float acc[2][8][4]) {
#pragma unroll
    for (int m = 0; m < 2; m++)
#pragma unroll
        for (int n = 0; n < 8; n++)
#pragma unroll
            for (int j = 0; j < 4; j++) acc[m][n][j] = 0.f;
#pragma unroll
    for (int s = 0; s < 4; s++) {
        const int kp = (s << 3) + t;
        uint32_t af[2][4], bf[8][2];
#pragma unroll
        for (int m = 0; m < 2; m++) {
            const uint32_t* ap = As + (size_t)(warpRow + (m << 4) + g) * KPW + kp;
            af[m][0] = ap[0];
            af[m][1] = ap[8 * KPW];
            af[m][2] = ap[4];
            af[m][3] = ap[8 * KPW + 4];
        }
#pragma unroll
        for (int n = 0; n < 8; n++) {
            const uint32_t* bp = Bs + (size_t)(warpCol + (n << 3) + g) * KPW + kp;
            bf[n][0] = bp[0];
            bf[n][1] = bp[4];
        }
#pragma unroll
        for (int m = 0; m < 2; m++)
#pragma unroll
            for (int n = 0; n < 8; n++) {
                asm volatile(
                    "mma.sync.aligned.m16n8k16.row.col.f32.bf16.bf16.f32 "
                    "{%0,%1,%2,%3}, {%4,%5,%6,%7}, {%8,%9}, {%0,%1,%2,%3};"
                    : "+f"(acc[m][n][0]), "+f"(acc[m][n][1]),
                      "+f"(acc[m][n][2]), "+f"(acc[m][n][3])
                    : "r"(af[m][0]), "r"(af[m][1]), "r"(af[m][2]), "r"(af[m][3]),
                      "r"(bf[n][0]), "r"(bf[n][1]));
            }
    }
}

// epilogue: direct stores + optional per-warpgroup staging (local col = c0 - warpCol)
__device__ __forceinline__ void epilogue_tile(float acc[2][8][4],
                                              const float* sqa, const float* sqb,
                                              float cc, float* out,
                                              int rowBase, int colBase,
                                              int warpRow, int warpCol, int g, int t,
                                              bool stage, float* stgw) {
    const float c2 = 2.f * cc;
#pragma unroll
    for (int m = 0; m < 2; m++) {
        const int r0 = warpRow + (m << 4) + g;
        const float u0 = -cc * sqa[r0], u1 = -cc * sqa[r0 + 8];
#pragma unroll
        for (int n = 0; n < 8; n++) {
            const int c0 = warpCol + (n << 3) + (t << 1);
            const int cl = (n << 3) + (t << 1);       // warpgroup-local col
            const float v0 = -cc * sqb[c0], v1 = -cc * sqb[c0 + 1];
            const float ws[4] = { u0 + v0, u0 + v1, u1 + v0, u1 + v1 };
            float r[4];
#pragma unroll
            for (int j = 0; j < 4; j++) {
                float y = fminf(fmaf(c2, acc[m][n][j], ws[j]), 0.f);
                float e;
                asm("ex2.approx.ftz.f32 %0, %1;" : "=f"(e) : "f"(y));
                float e2 = e * e;
                float s = e + e2;
                float e4 = e2 * e2;
                s = fmaf(e2, e2, s);
                s = fmaf(e4, e4, s);
                float e8 = e4 * e4;
                s = fmaf(e8, e8, s);
                r[j] = s;
            }
            float* o0 = out + (size_t)(rowBase + r0) * NPTS + colBase + c0;
            float* o1 = out + (size_t)(rowBase + r0 + 8) * NPTS + colBase + c0;
            *(float2*)o0 = make_float2(r[0], r[1]);
            *(float2*)o1 = make_float2(r[2], r[3]);
            if (stage) {
                stgw[(cl)     * SLD + r0]     = r[0];
                stgw[(cl + 1) * SLD + r0]     = r[1];
                stgw[(cl)     * SLD + r0 + 8] = r[2];
                stgw[(cl + 1) * SLD + r0 + 8] = r[3];
            }
        }
    }
}

// mirror 64 staged cols (one warpgroup, 4 warps): output rows colBase64+c, cols rowBase+r
__device__ __forceinline__ void mirror_half(const float* stgw, float* out,
                                            int rowBase, int colBase64,
                                            int ww, int lane) {
    const int c_off = lane >> 3, r_off = (lane & 7) << 2;
#pragma unroll
    for (int i = 0; i < 16; i++) {
        int c = (ww << 4) + ((i & 3) << 2) + c_off;
        int r = ((i >> 2) << 5) + r_off;
        float4 v = *(const float4*)&stgw[c * SLD + r];
        *(float4*)(out + (size_t)(colBase64 + c) * NPTS + rowBase + r) = v;
    }
}

// smem words: As@0(4608) | B1s@4608(4608) | stg@9216(2x8448; B2 halves alias stg starts)
__global__ __launch_bounds__(256, 2)
void rbf_fused_kernel(const float* __restrict__ X, float* __restrict__ out) {
    extern __shared__ uint32_t smw[];
    uint32_t* As  = smw;
    uint32_t* B1s = smw + 4608;
    __shared__ float sqa[128], sqb1[128], sqb2[128];
    __shared__ float red[256];
    __shared__ float colp[8][64];
    __shared__ float s_c[2];
    __shared__ int   s_last;

    const int tid = threadIdx.x;
    const int wid = tid >> 5, lane = tid & 31;
    const int wg  = wid >> 2, ww = wid & 3, wg_tid = tid & 127;
    const int bid = blockIdx.x;

    uint32_t* B2w  = smw + 9216 + wg * 8448;
    float*    stgw = (float*)B2w;

    // pair-tile decode: bid -> (bi, p); tiles (bi, 2p) [if valid] and (bi, 2p+1)
    int bi = 0, rr = bid;
    while (rr >= 16 - (bi >> 1)) { rr -= 16 - (bi >> 1); bi++; }
    const int p = (bi >> 1) + rr;
    const bool two = (2 * p >= bi);
    const int bj1 = two ? 2 * p : 2 * p + 1;
    const int bj2 = 2 * p + 1;
    const bool diag1 = (bj1 == bi);
    const int rowBase = bi << 7, colBase1 = bj1 << 7, colBase2 = bj2 << 7;

    // ===== phase 0: bandwidth duty on the 16 single-tile (diagonal) CTAs =====
    if (!two) {
        const int duty = bi >> 1;
        const int base = duty << 8;
        const int q = tid & 3;
        float v[16];
#pragma unroll
        for (int i = 0; i < 16; i++) v[i] = 0.f;
        float s = 0.f;
#pragma unroll
        for (int b = 0; b < 4; b++) {
            const int row = base + (b << 6) + (tid >> 2);
            const float4* pp = (const float4*)(X + (size_t)row * DDIM + q * 16);
#pragma unroll
            for (int i = 0; i < 4; i++) {
                float4 f = pp[i];
                v[i * 4 + 0] += f.x; v[i * 4 + 1] += f.y;
                v[i * 4 + 2] += f.z; v[i * 4 + 3] += f.w;
                s += f.x * f.x + f.y * f.y + f.z * f.z + f.w * f.w;
            }
        }
        red[tid] = s;
        __syncthreads();
#pragma unroll
        for (int off = 128; off > 0; off >>= 1) {
            if (tid < off) red[tid] += red[tid + off];
            __syncthreads();
        }
        if (tid == 0) g_partial_sq[duty] = red[0];
#pragma unroll
        for (int stp = 4; stp <= 16; stp <<= 1)
#pragma unroll
            for (int i = 0; i < 16; i++)
                v[i] += __shfl_xor_sync(0xffffffffu, v[i], stp);
        if (lane < 4) {
#pragma unroll
            for (int i = 0; i < 16; i++) colp[wid][lane * 16 + i] = v[i];
        }
        __syncthreads();
        if (tid < 64) {
            float t = 0.f;
#pragma unroll
            for (int w = 0; w < 8; w++) t += colp[w][tid];
            g_partial_col[duty][tid] = t;
        }
        __threadfence();
        if (tid == 0) {
            int r = atomicAdd(&g_arrive, 1);
            s_last = (r == NDUTY - 1);
        }
        __syncthreads();
        if (s_last) {
            if (tid < 64) {
                float cs = 0.f;
#pragma unroll
                for (int b = 0; b < NDUTY; b++) cs += g_partial_col[b][tid];
                red[tid] = cs * cs;
                red[128 + tid] = (tid < NDUTY) ? g_partial_sq[tid] : 0.f;
            }
            __syncthreads();
#pragma unroll
            for (int off = 32; off > 0; off >>= 1) {
                if (tid < off) { red[tid] += red[tid + off]; red[128 + tid] += red[128 + tid + off]; }
                __syncthreads();
            }
            if (tid == 0) {
                // sum(L2) = 2*N*sum(||xi||^2) - 2*||sum xi||^2 (clamp negligible)
                float bwsum = 2.f * (float)NPTS * red[128] - 2.f * red[0];
                float bw = bwsum / ((float)NPTS * (float)(NPTS - 1));
                g_c = 1.4426950408889634f / (4.f * bw);
                __threadfence();
                asm volatile("st.release.gpu.b32 [%0], %1;" :: "l"(&g_flag), "r"(1u) : "memory");
            }
        }
        __syncthreads();
    }

    // ===== phase 1: fill A + B1 tiles (bf16 kpairs) + norms, block-wide =====
#pragma unroll
    for (int i = 0; i < 8; i++) {
        int idx = tid + (i << 8);
        int r = idx >> 4, f = idx & 15;
        float4 va = *(const float4*)(X + (size_t)(rowBase + r) * DDIM + (f << 2));
        float4 vb = *(const float4*)(X + (size_t)(colBase1 + r) * DDIM + (f << 2));
        float da = va.x * va.x + va.y * va.y + va.z * va.z + va.w * va.w;
        float db = vb.x * vb.x + vb.y * vb.y + vb.z * vb.z + vb.w * vb.w;
#pragma unroll
        for (int stp = 1; stp <= 8; stp <<= 1) {
            da += __shfl_xor_sync(0xffffffffu, da, stp);
            db += __shfl_xor_sync(0xffffffffu, db, stp);
        }
        if ((lane & 15) == 0) { sqa[r] = da; sqb1[r] = db; }
        const int off = r * KPW + (f << 1);
        *(uint2*)(As + off)  = make_uint2(bf2(va.x, va.y), bf2(va.z, va.w));
        *(uint2*)(B1s + off) = make_uint2(bf2(vb.x, vb.y), bf2(vb.z, vb.w));
    }
    __syncthreads();   // last block-wide sync until the end

    // ===== from here the two warpgroups run independently =====
    const int g = lane >> 2, t = lane & 3;
    const int warpRow = ww << 5;
    const int warpCol = wg << 6;

    float acc[2][8][4];
    mma_tile(As, B1s, warpRow, warpCol, g, t, acc);

    // prefetch this warpgroup's B2 half (64 rows) into registers
    float4 pb[8];
    if (two) {
#pragma unroll
        for (int i = 0; i < 8; i++) {
            int idx = wg_tid + (i << 7);
            int rl = idx >> 4, f = idx & 15;
            pb[i] = *(const float4*)(X + (size_t)(colBase2 + (wg << 6) + rl) * DDIM + (f << 2));
        }
    }

    // wait for g_c (usually already set)
    if (wg_tid == 0) {
        unsigned int f;
        do {
            asm volatile("ld.acquire.gpu.b32 %0, [%1];" : "=r"(f) : "l"(&g_flag) : "memory");
        } while (f == 0);
        s_c[wg] = g_c;
    }
    WGBAR(wg);
    const float cc = s_c[wg];

    // ===== tile 1: epilogue (+ stage) and mirror of this warpgroup's 64 cols =====
    epilogue_tile(acc, sqa, sqb1, cc, out, rowBase, colBase1,
                  warpRow, warpCol, g, t, !diag1, stgw);
    if (!diag1) {
        WGBAR(wg);
        mirror_half(stgw, out, rowBase, colBase1 + (wg << 6), ww, lane);
    }

    // ===== tile 2 =====
    if (two) {
        WGBAR(wg);   // mirror1 stg reads done before B2 half overwrites stgw start
#pragma unroll
        for (int i = 0; i < 8; i++) {
            int idx = wg_tid + (i << 7);
            int rl = idx >> 4, f = idx & 15;
            float4 vb = pb[i];
            float db = vb.x * vb.x + vb.y * vb.y + vb.z * vb.z + vb.w * vb.w;
#pragma unroll
            for (int stp = 1; stp <= 8; stp <<= 1)
                db += __shfl_xor_sync(0xffffffffu, db, stp);
            if ((lane & 15) == 0) sqb2[(wg << 6) + rl] = db;
            *(uint2*)(B2w + rl * KPW + (f << 1)) = make_uint2(bf2(vb.x, vb.y), bf2(vb.z, vb.w));
        }
        WGBAR(wg);

        // B2w holds rows [64wg..64wg+63] at local offsets; bias pointer so
        // (warpCol + n*8 + g) indexing lands on local rows
        mma_tile(As, B2w - (size_t)(wg << 6) * KPW, warpRow, warpCol, g, t, acc);
        WGBAR(wg);   // MMA2 B2w reads done before epilogue2 staging overwrites

        epilogue_tile(acc, sqa, sqb2, cc, out, rowBase, colBase2,
                      warpRow, warpCol, g, t, true, stgw);
        WGBAR(wg);
        mirror_half(stgw, out, rowBase, colBase2 + (wg << 6), ww, lane);
    }

    // ===== final: last CTA resets counters for next replay =====
    __syncthreads();
    if (tid == 0) {
        int d = atomicAdd(&g_done, 1);
        if (d == NBLOCKS - 1) {
            g_arrive = 0;
            g_done = 0;
            asm volatile("st.relaxed.gpu.b32 [%0], %1;" :: "l"(&g_flag), "r"(0u) : "memory");
        }
    }
}

// ---------------- launch ----------------
extern "C" void kernel_launch(void* const* d_in, const int* in_sizes, int n_in,
                              void* d_out, int out_size) {
    const float* X = (const float*)d_in[0];
    float* out = (float*)d_out;

    const int smem_bytes = (9216 + 2 * 8448) * 4;   // 104448 B
    cudaFuncSetAttribute(rbf_fused_kernel, cudaFuncAttributeMaxDynamicSharedMemorySize, smem_bytes);

    rbf_fused_kernel<<<NBLOCKS, 256, smem_bytes>>>(X, out);
}